// round 3
// baseline (speedup 1.0000x reference)
#include <cuda_runtime.h>
#include <math.h>
#include <stdint.h>

#define B_ 4
#define T_ 1024
#define D_ 1024
#define H_ 16
#define HD_ 64
#define BH_ 64

// ---------------- scratch (__device__ globals; no allocations allowed) -----
__device__ float g_h[B_*T_*D_];
__device__ float g_q[B_*T_*D_];
__device__ float g_k[B_*T_*D_];
__device__ float g_v[B_*T_*D_];
__device__ float g_ctx[B_*T_*D_];
__device__ float g_gate[BH_*T_];
__device__ float g_pb[H_*2048];
__device__ float g_scores[67108864];   // B*H*T*T fp32 = 256 MB

// ---------------- helpers ---------------------------------------------------
__device__ __forceinline__ float warp_sum(float v) {
    #pragma unroll
    for (int o = 16; o > 0; o >>= 1) v += __shfl_xor_sync(0xffffffffu, v, o);
    return v;
}
__device__ __forceinline__ float warp_max(float v) {
    #pragma unroll
    for (int o = 16; o > 0; o >>= 1) v = fmaxf(v, __shfl_xor_sync(0xffffffffu, v, o));
    return v;
}

// ---------------- LayerNorm: one block per row ------------------------------
__global__ void ln_kernel(const float* __restrict__ x, const float* __restrict__ w,
                          const float* __restrict__ bb, float* __restrict__ out)
{
    int row = blockIdx.x, tid = threadIdx.x;
    const float4* xr = (const float4*)(x + (size_t)row * D_);
    float4 v = xr[tid];
    float s  = v.x + v.y + v.z + v.w;
    float s2 = v.x*v.x + v.y*v.y + v.z*v.z + v.w*v.w;
    __shared__ float sm1[8], sm2[8];
    __shared__ float mu_s, inv_s;
    s = warp_sum(s); s2 = warp_sum(s2);
    if ((tid & 31) == 0) { sm1[tid >> 5] = s; sm2[tid >> 5] = s2; }
    __syncthreads();
    if (tid == 0) {
        float ts = 0.f, ts2 = 0.f;
        #pragma unroll
        for (int i = 0; i < 8; i++) { ts += sm1[i]; ts2 += sm2[i]; }
        float mu = ts / (float)D_;
        float var = ts2 / (float)D_ - mu * mu;
        mu_s = mu; inv_s = rsqrtf(var + 1e-5f);
    }
    __syncthreads();
    float mu = mu_s, inv = inv_s;
    float4 wv = ((const float4*)w)[tid];
    float4 bv = ((const float4*)bb)[tid];
    float4 o;
    o.x = (v.x - mu) * inv * wv.x + bv.x;
    o.y = (v.y - mu) * inv * wv.y + bv.y;
    o.z = (v.z - mu) * inv * wv.z + bv.z;
    o.w = (v.w - mu) * inv * wv.w + bv.w;
    ((float4*)(out + (size_t)row * D_))[tid] = o;
}

// ---------------- SGEMM NT: C = alpha*(A·B^T + bias) [+ resid] --------------
// A: MxK row-major, B: NxK row-major, C/resid: MxN row-major. 128x128x8, 8x8/thr.
__global__ void __launch_bounds__(256) sgemm_nt(
    const float* __restrict__ A, const float* __restrict__ Bm,
    const float* __restrict__ bias, const float* __restrict__ resid,
    float alpha, float* __restrict__ C, int M, int N, int K)
{
    __shared__ float As[8][128];
    __shared__ float Bs[8][128];
    int tid = threadIdx.x;
    int bm = blockIdx.y * 128, bn = blockIdx.x * 128;
    int lrow = tid >> 1, lk = (tid & 1) * 4;
    const float* Ap = A + (size_t)(bm + lrow) * K + lk;
    const float* Bp = Bm + (size_t)(bn + lrow) * K + lk;
    int tx = tid & 15, ty = tid >> 4;
    float acc[8][8];
    #pragma unroll
    for (int i = 0; i < 8; i++)
        #pragma unroll
        for (int j = 0; j < 8; j++) acc[i][j] = 0.f;

    for (int k0 = 0; k0 < K; k0 += 8) {
        float4 a4 = *(const float4*)(Ap + k0);
        float4 b4 = *(const float4*)(Bp + k0);
        As[lk+0][lrow] = a4.x; As[lk+1][lrow] = a4.y; As[lk+2][lrow] = a4.z; As[lk+3][lrow] = a4.w;
        Bs[lk+0][lrow] = b4.x; Bs[lk+1][lrow] = b4.y; Bs[lk+2][lrow] = b4.z; Bs[lk+3][lrow] = b4.w;
        __syncthreads();
        #pragma unroll
        for (int kk = 0; kk < 8; kk++) {
            float a[8], b[8];
            *(float4*)(a)   = *(const float4*)&As[kk][ty*8];
            *(float4*)(a+4) = *(const float4*)&As[kk][ty*8+4];
            *(float4*)(b)   = *(const float4*)&Bs[kk][tx*8];
            *(float4*)(b+4) = *(const float4*)&Bs[kk][tx*8+4];
            #pragma unroll
            for (int i = 0; i < 8; i++)
                #pragma unroll
                for (int j = 0; j < 8; j++) acc[i][j] += a[i] * b[j];
        }
        __syncthreads();
    }
    #pragma unroll
    for (int i = 0; i < 8; i++) {
        int m = bm + ty*8 + i;
        #pragma unroll
        for (int j = 0; j < 8; j++) {
            int n = bn + tx*8 + j;
            float vv = (acc[i][j] + bias[n]) * alpha;
            if (resid) vv += resid[(size_t)m * N + n];
            C[(size_t)m * N + n] = vv;
        }
    }
}

// ---------------- grep gate: one warp per (b,h,t) ---------------------------
__global__ void gate_kernel(const float* __restrict__ q, const float* __restrict__ gw,
                            const float* __restrict__ gb, const float* __restrict__ ga,
                            float* __restrict__ gate)
{
    __shared__ float sgw[8][64];
    int tid = threadIdx.x;
    ((float*)sgw)[tid]       = gw[tid];
    ((float*)sgw)[tid + 256] = gw[tid + 256];
    __syncthreads();
    int warp = tid >> 5, lane = tid & 31;
    size_t z = (size_t)blockIdx.x * 8 + warp;      // 0 .. B*H*T-1
    int t = (int)(z % T_);
    int h = (int)((z / T_) % H_);
    int b = (int)(z / ((size_t)H_ * T_));
    const float* qr = q + ((size_t)b * T_ + t) * D_ + h * HD_;
    float q0 = qr[lane] * 256.f;        // alpha/scaling = 32 / 64^-0.5 = 256
    float q1 = qr[lane + 32] * 256.f;
    float y[8];
    #pragma unroll
    for (int j = 0; j < 8; j++)
        y[j] = q0 * sgw[j][lane] + q1 * sgw[j][lane + 32];
    #pragma unroll
    for (int o = 16; o > 0; o >>= 1)
        #pragma unroll
        for (int j = 0; j < 8; j++) y[j] += __shfl_xor_sync(0xffffffffu, y[j], o);
    if (lane == 0) {
        float s0 = y[0]+y[1]+y[2]+y[3] + gb[0]+gb[1]+gb[2]+gb[3];
        float s1 = y[4]+y[5]+y[6]+y[7] + gb[4]+gb[5]+gb[6]+gb[7];
        float ga_ = 1.f / (1.f + expf(-s0));
        float gbv = 1.f / (1.f + expf(-s1));
        gate[z] = ga_ * (gbv * ga[h] - 1.f) + 2.f;
    }
}

// ---------------- relative-position bias table: pb[h][rel+1023] -------------
__global__ void pbtable_kernel(const float* __restrict__ rel_emb, float* __restrict__ pb)
{
    int i = blockIdx.x * 256 + threadIdx.x;
    if (i >= 2048) return;
    if (i == 2047) {        // padding entry (rel=1024, never referenced by valid elems)
        for (int h = 0; h < H_; h++) pb[h * 2048 + i] = 0.f;
        return;
    }
    int rel = i - 1023;
    int bucket = (rel > 0) ? 160 : 0;
    int n = abs(rel);
    int idx;
    if (n < 80) {
        idx = bucket + n;
    } else {
        double nf = (double)n;
        int large = 80 + (int)(log(nf / 80.0) / log(10.0) * 80.0);
        if (large > 159) large = 159;
        idx = bucket + large;
    }
    for (int h = 0; h < H_; h++) pb[h * 2048 + i] = rel_emb[idx * H_ + h];
}

// ---------------- pos_bias_out writer: (B*H, T, T) broadcast ----------------
__global__ void posbias_kernel(const float* __restrict__ pb, float* __restrict__ out)
{
    size_t gid = (size_t)blockIdx.x * 256 + threadIdx.x;  // float4 units, 16M total
    int s4 = (int)(gid & 255);
    int t  = (int)((gid >> 8) & 1023);
    int bh = (int)(gid >> 18);
    int h  = bh & 15;
    const float* row = pb + h * 2048 + 1023 - t;
    int s = s4 * 4;
    float4 o = make_float4(row[s], row[s+1], row[s+2], row[s+3]);
    ((float4*)out)[gid] = o;
}

// ---------------- batched QK^T + gate*pb epilogue ---------------------------
// grid (T/128, T/128, BH); q/k head slices with row stride D, K=64.
__global__ void __launch_bounds__(256) qk_scores(
    const float* __restrict__ q, const float* __restrict__ k,
    const float* __restrict__ gate, const float* __restrict__ pb,
    float* __restrict__ scores)
{
    int z = blockIdx.z;
    int b = z / H_, h = z % H_;
    const float* A  = q + (size_t)b * T_ * D_ + h * HD_;
    const float* Bm = k + (size_t)b * T_ * D_ + h * HD_;
    float* C = scores + (size_t)z * T_ * T_;

    __shared__ float As[8][128];
    __shared__ float Bs[8][128];
    __shared__ float pbs[256];
    __shared__ float gs[128];

    int tid = threadIdx.x;
    int bm = blockIdx.y * 128, bn = blockIdx.x * 128;
    int base = bn - bm + 896;           // (s - t + 1023) at tile corner minus 127
    pbs[tid] = pb[h * 2048 + base + tid];
    if (tid < 128) gs[tid] = gate[(size_t)z * T_ + bm + tid];

    int lrow = tid >> 1, lk = (tid & 1) * 4;
    const float* Ap = A + (size_t)(bm + lrow) * D_ + lk;
    const float* Bp = Bm + (size_t)(bn + lrow) * D_ + lk;
    int tx = tid & 15, ty = tid >> 4;
    float acc[8][8];
    #pragma unroll
    for (int i = 0; i < 8; i++)
        #pragma unroll
        for (int j = 0; j < 8; j++) acc[i][j] = 0.f;

    for (int k0 = 0; k0 < HD_; k0 += 8) {
        float4 a4 = *(const float4*)(Ap + k0);
        float4 b4 = *(const float4*)(Bp + k0);
        As[lk+0][lrow] = a4.x; As[lk+1][lrow] = a4.y; As[lk+2][lrow] = a4.z; As[lk+3][lrow] = a4.w;
        Bs[lk+0][lrow] = b4.x; Bs[lk+1][lrow] = b4.y; Bs[lk+2][lrow] = b4.z; Bs[lk+3][lrow] = b4.w;
        __syncthreads();
        #pragma unroll
        for (int kk = 0; kk < 8; kk++) {
            float a[8], bb[8];
            *(float4*)(a)    = *(const float4*)&As[kk][ty*8];
            *(float4*)(a+4)  = *(const float4*)&As[kk][ty*8+4];
            *(float4*)(bb)   = *(const float4*)&Bs[kk][tx*8];
            *(float4*)(bb+4) = *(const float4*)&Bs[kk][tx*8+4];
            #pragma unroll
            for (int i = 0; i < 8; i++)
                #pragma unroll
                for (int j = 0; j < 8; j++) acc[i][j] += a[i] * bb[j];
        }
        __syncthreads();
    }
    #pragma unroll
    for (int i = 0; i < 8; i++) {
        int m = ty*8 + i;
        float gv = gs[m];
        #pragma unroll
        for (int j = 0; j < 8; j++) {
            int n = tx*8 + j;
            float vv = acc[i][j] + gv * pbs[n - m + 127];
            C[(size_t)(bm + m) * T_ + bn + n] = vv;
        }
    }
}

// ---------------- row softmax, in place -------------------------------------
__global__ void softmax_kernel(float* __restrict__ s)
{
    size_t row = blockIdx.x;
    float4* p = (float4*)(s + row * (size_t)T_);
    int tid = threadIdx.x;
    float4 v = p[tid];
    __shared__ float sm[8];
    __shared__ float bmax, bsum;
    float m = fmaxf(fmaxf(v.x, v.y), fmaxf(v.z, v.w));
    m = warp_max(m);
    if ((tid & 31) == 0) sm[tid >> 5] = m;
    __syncthreads();
    if (tid == 0) {
        float t = sm[0];
        #pragma unroll
        for (int i = 1; i < 8; i++) t = fmaxf(t, sm[i]);
        bmax = t;
    }
    __syncthreads();
    m = bmax;
    float4 e;
    e.x = expf(v.x - m); e.y = expf(v.y - m); e.z = expf(v.z - m); e.w = expf(v.w - m);
    float su = e.x + e.y + e.z + e.w;
    su = warp_sum(su);
    __syncthreads();                     // protect sm reuse
    if ((tid & 31) == 0) sm[tid >> 5] = su;
    __syncthreads();
    if (tid == 0) {
        float t = 0.f;
        #pragma unroll
        for (int i = 0; i < 8; i++) t += sm[i];
        bsum = 1.f / t;
    }
    __syncthreads();
    float inv = bsum;
    e.x *= inv; e.y *= inv; e.z *= inv; e.w *= inv;
    p[tid] = e;
}

// ---------------- batched attn·V (NN): ctx[t,d] = sum_s attn[t,s] v[s,d] ----
// grid (1, T/128, BH). BM=128, BN=64, BK=32, 256 thr, 8x4/thr.
__global__ void __launch_bounds__(256) av_gemm(
    const float* __restrict__ attn, const float* __restrict__ v, float* __restrict__ ctx)
{
    int z = blockIdx.z;
    int b = z / H_, h = z % H_;
    const float* A  = attn + (size_t)z * T_ * T_;              // lda = T
    const float* Bm = v + (size_t)b * T_ * D_ + h * HD_;       // ldb = D
    float* C = ctx + (size_t)b * T_ * D_ + h * HD_;            // ldc = D

    __shared__ float As[32][128];   // [k][m]
    __shared__ float Bs[32][64];    // [k][n]
    int tid = threadIdx.x;
    int bm = blockIdx.y * 128;
    int tx = tid & 15, ty = tid >> 4;
    int arow = tid >> 1, akb = (tid & 1) * 16;
    int bkr = tid >> 4, bcol = (tid & 15) * 4;

    float acc[8][4];
    #pragma unroll
    for (int i = 0; i < 8; i++)
        #pragma unroll
        for (int j = 0; j < 4; j++) acc[i][j] = 0.f;

    for (int k0 = 0; k0 < T_; k0 += 32) {
        #pragma unroll
        for (int i = 0; i < 4; i++) {
            float4 a4 = *(const float4*)(A + (size_t)(bm + arow) * T_ + k0 + akb + i*4);
            As[akb + i*4 + 0][arow] = a4.x;
            As[akb + i*4 + 1][arow] = a4.y;
            As[akb + i*4 + 2][arow] = a4.z;
            As[akb + i*4 + 3][arow] = a4.w;
        }
        #pragma unroll
        for (int i = 0; i < 2; i++) {
            int kr = bkr + i * 16;
            float4 b4 = *(const float4*)(Bm + (size_t)(k0 + kr) * D_ + bcol);
            *(float4*)&Bs[kr][bcol] = b4;
        }
        __syncthreads();
        #pragma unroll
        for (int kk = 0; kk < 32; kk++) {
            float a[8], bb[4];
            *(float4*)(a)   = *(const float4*)&As[kk][ty*8];
            *(float4*)(a+4) = *(const float4*)&As[kk][ty*8+4];
            *(float4*)(bb)  = *(const float4*)&Bs[kk][tx*4];
            #pragma unroll
            for (int i = 0; i < 8; i++)
                #pragma unroll
                for (int j = 0; j < 4; j++) acc[i][j] += a[i] * bb[j];
        }
        __syncthreads();
    }
    #pragma unroll
    for (int i = 0; i < 8; i++) {
        float4 o = make_float4(acc[i][0], acc[i][1], acc[i][2], acc[i][3]);
        *(float4*)&C[(size_t)(bm + ty*8 + i) * D_ + tx*4] = o;
    }
}

// ---------------- host launcher ---------------------------------------------
extern "C" void kernel_launch(void* const* d_in, const int* in_sizes, int n_in,
                              void* d_out, int out_size)
{
    const float* x      = (const float*)d_in[0];
    const float* ln_w   = (const float*)d_in[1];
    const float* ln_b   = (const float*)d_in[2];
    const float* wq     = (const float*)d_in[3];
    const float* bq     = (const float*)d_in[4];
    const float* wk     = (const float*)d_in[5];
    const float* bk     = (const float*)d_in[6];
    const float* wv     = (const float*)d_in[7];
    const float* bv     = (const float*)d_in[8];
    const float* wo     = (const float*)d_in[9];
    const float* bo     = (const float*)d_in[10];
    const float* rel_e  = (const float*)d_in[11];
    const float* grep_w = (const float*)d_in[12];
    const float* grep_b = (const float*)d_in[13];
    const float* grep_a = (const float*)d_in[14];

    float* out     = (float*)d_out;
    float* pos_out = out + (size_t)B_ * T_ * D_;

    float *p_h, *p_q, *p_k, *p_v, *p_ctx, *p_gate, *p_pb, *p_sc;
    cudaGetSymbolAddress((void**)&p_h,    g_h);
    cudaGetSymbolAddress((void**)&p_q,    g_q);
    cudaGetSymbolAddress((void**)&p_k,    g_k);
    cudaGetSymbolAddress((void**)&p_v,    g_v);
    cudaGetSymbolAddress((void**)&p_ctx,  g_ctx);
    cudaGetSymbolAddress((void**)&p_gate, g_gate);
    cudaGetSymbolAddress((void**)&p_pb,   g_pb);
    cudaGetSymbolAddress((void**)&p_sc,   g_scores);

    // 1. LayerNorm
    ln_kernel<<<B_*T_, 256>>>(x, ln_w, ln_b, p_h);

    // 2. QKV projections (NT GEMMs); q carries scaling = 64^-0.5
    dim3 g1(D_/128, (B_*T_)/128);
    sgemm_nt<<<g1, 256>>>(p_h, wq, bq, nullptr, 0.125f, p_q, B_*T_, D_, D_);
    sgemm_nt<<<g1, 256>>>(p_h, wk, bk, nullptr, 1.0f,   p_k, B_*T_, D_, D_);
    sgemm_nt<<<g1, 256>>>(p_h, wv, bv, nullptr, 1.0f,   p_v, B_*T_, D_, D_);

    // 3. grep gate
    gate_kernel<<<(BH_*T_)/8, 256>>>(p_q, grep_w, grep_b, grep_a, p_gate);

    // 4. rel-position bias table + broadcast output
    pbtable_kernel<<<8, 256>>>(rel_e, p_pb);
    posbias_kernel<<<65536, 256>>>(p_pb, pos_out);

    // 5. scores = q k^T + gate * pos_bias
    qk_scores<<<dim3(T_/128, T_/128, BH_), 256>>>(p_q, p_k, p_gate, p_pb, p_sc);

    // 6. softmax over last dim
    softmax_kernel<<<BH_*T_, 256>>>(p_sc);

    // 7. ctx = attn @ v   (written directly in (B,T,D) layout)
    av_gemm<<<dim3(1, T_/128, BH_), 256>>>(p_sc, p_v, p_ctx);

    // 8. out = ctx @ wo^T + bo + x
    sgemm_nt<<<g1, 256>>>(p_ctx, wo, bo, x, 1.0f, out, B_*T_, D_, D_);
}

// round 4
// speedup vs baseline: 1.4356x; 1.4356x over previous
#include <cuda_runtime.h>
#include <math.h>
#include <stdint.h>

#define B_ 4
#define T_ 1024
#define D_ 1024
#define H_ 16
#define HD_ 64
#define BH_ 64
#define PAD 132

// ---------------- scratch (__device__ globals; no allocations allowed) -----
__device__ float g_h[B_*T_*D_];
__device__ float g_q[B_*T_*D_];
__device__ float g_k[B_*T_*D_];
__device__ float g_v[B_*T_*D_];
__device__ float g_ctx[B_*T_*D_];
__device__ float g_gate[BH_*T_];
__device__ float g_pb[H_*2048];
__device__ float2 g_stats[BH_*T_];
__device__ float g_scores[67108864];   // B*H*T*T fp32 = 256 MB

// ---------------- helpers ---------------------------------------------------
__device__ __forceinline__ float warp_sum(float v) {
    #pragma unroll
    for (int o = 16; o > 0; o >>= 1) v += __shfl_xor_sync(0xffffffffu, v, o);
    return v;
}
__device__ __forceinline__ float warp_max(float v) {
    #pragma unroll
    for (int o = 16; o > 0; o >>= 1) v = fmaxf(v, __shfl_xor_sync(0xffffffffu, v, o));
    return v;
}

// ---------------- LayerNorm: one block per row ------------------------------
__global__ void ln_kernel(const float* __restrict__ x, const float* __restrict__ w,
                          const float* __restrict__ bb, float* __restrict__ out)
{
    int row = blockIdx.x, tid = threadIdx.x;
    const float4* xr = (const float4*)(x + (size_t)row * D_);
    float4 v = xr[tid];
    float s  = v.x + v.y + v.z + v.w;
    float s2 = v.x*v.x + v.y*v.y + v.z*v.z + v.w*v.w;
    __shared__ float sm1[8], sm2[8];
    __shared__ float mu_s, inv_s;
    s = warp_sum(s); s2 = warp_sum(s2);
    if ((tid & 31) == 0) { sm1[tid >> 5] = s; sm2[tid >> 5] = s2; }
    __syncthreads();
    if (tid == 0) {
        float ts = 0.f, ts2 = 0.f;
        #pragma unroll
        for (int i = 0; i < 8; i++) { ts += sm1[i]; ts2 += sm2[i]; }
        float mu = ts / (float)D_;
        float var = ts2 / (float)D_ - mu * mu;
        mu_s = mu; inv_s = rsqrtf(var + 1e-5f);
    }
    __syncthreads();
    float mu = mu_s, inv = inv_s;
    float4 wv = ((const float4*)w)[tid];
    float4 bv = ((const float4*)bb)[tid];
    float4 o;
    o.x = (v.x - mu) * inv * wv.x + bv.x;
    o.y = (v.y - mu) * inv * wv.y + bv.y;
    o.z = (v.z - mu) * inv * wv.z + bv.z;
    o.w = (v.w - mu) * inv * wv.w + bv.w;
    ((float4*)(out + (size_t)row * D_))[tid] = o;
}

// ---------------- SGEMM NT, double-buffered, conflict-free fragments --------
// C = alpha*(A·B^T + bias) [+ resid].  A: MxK rm, B: NxK rm.  128x128x16.
// Thread tile: rows {ty*4..+3, 64+ty*4..+3} x cols {tx*4..+3, 64+tx*4..+3}.
__global__ void __launch_bounds__(256, 2) sgemm_nt_db(
    const float* __restrict__ A, const float* __restrict__ Bm,
    const float* __restrict__ bias, const float* __restrict__ resid,
    float alpha, float* __restrict__ C, int M, int N, int K)
{
    __shared__ float As[2][16][PAD];
    __shared__ float Bs[2][16][PAD];
    int tid = threadIdx.x;
    int bm = blockIdx.y * 128, bn = blockIdx.x * 128;
    int r0 = tid >> 2;             // 0..63
    int kc = (tid & 3) * 4;
    const float* Ap = A + (size_t)(bm + r0) * K + kc;
    const float* Bp = Bm + (size_t)(bn + r0) * K + kc;
    int tx = tid & 15, ty = tid >> 4;

    float acc[8][8] = {};
    float4 ra0, ra1, rb0, rb1;

    // prologue: tile 0
    ra0 = *(const float4*)(Ap);
    ra1 = *(const float4*)(Ap + (size_t)64 * K);
    rb0 = *(const float4*)(Bp);
    rb1 = *(const float4*)(Bp + (size_t)64 * K);
    #pragma unroll
    for (int j = 0; j < 4; j++) {
        As[0][kc+j][r0]    = ((float*)&ra0)[j];
        As[0][kc+j][r0+64] = ((float*)&ra1)[j];
        Bs[0][kc+j][r0]    = ((float*)&rb0)[j];
        Bs[0][kc+j][r0+64] = ((float*)&rb1)[j];
    }
    __syncthreads();

    int nkt = K >> 4;
    int buf = 0;
    for (int kt = 0; kt < nkt; ++kt) {
        if (kt + 1 < nkt) {
            const float* Ap2 = Ap + (kt + 1) * 16;
            const float* Bp2 = Bp + (kt + 1) * 16;
            ra0 = *(const float4*)(Ap2);
            ra1 = *(const float4*)(Ap2 + (size_t)64 * K);
            rb0 = *(const float4*)(Bp2);
            rb1 = *(const float4*)(Bp2 + (size_t)64 * K);
        }
        #pragma unroll
        for (int kk = 0; kk < 16; kk++) {
            float a[8], b[8];
            *(float4*)(a)   = *(const float4*)&As[buf][kk][ty*4];
            *(float4*)(a+4) = *(const float4*)&As[buf][kk][64 + ty*4];
            *(float4*)(b)   = *(const float4*)&Bs[buf][kk][tx*4];
            *(float4*)(b+4) = *(const float4*)&Bs[buf][kk][64 + tx*4];
            #pragma unroll
            for (int i = 0; i < 8; i++)
                #pragma unroll
                for (int j = 0; j < 8; j++) acc[i][j] += a[i] * b[j];
        }
        if (kt + 1 < nkt) {
            buf ^= 1;
            #pragma unroll
            for (int j = 0; j < 4; j++) {
                As[buf][kc+j][r0]    = ((float*)&ra0)[j];
                As[buf][kc+j][r0+64] = ((float*)&ra1)[j];
                Bs[buf][kc+j][r0]    = ((float*)&rb0)[j];
                Bs[buf][kc+j][r0+64] = ((float*)&rb1)[j];
            }
            __syncthreads();
        }
    }

    float4 blo = *(const float4*)&bias[bn + tx*4];
    float4 bhi = *(const float4*)&bias[bn + 64 + tx*4];
    #pragma unroll
    for (int i = 0; i < 8; i++) {
        int m = bm + ((i < 4) ? (ty*4 + i) : (64 + ty*4 + i - 4));
        float4 olo, ohi;
        olo.x = (acc[i][0] + blo.x) * alpha;
        olo.y = (acc[i][1] + blo.y) * alpha;
        olo.z = (acc[i][2] + blo.z) * alpha;
        olo.w = (acc[i][3] + blo.w) * alpha;
        ohi.x = (acc[i][4] + bhi.x) * alpha;
        ohi.y = (acc[i][5] + bhi.y) * alpha;
        ohi.z = (acc[i][6] + bhi.z) * alpha;
        ohi.w = (acc[i][7] + bhi.w) * alpha;
        if (resid) {
            float4 r1 = *(const float4*)&resid[(size_t)m * N + bn + tx*4];
            float4 r2 = *(const float4*)&resid[(size_t)m * N + bn + 64 + tx*4];
            olo.x += r1.x; olo.y += r1.y; olo.z += r1.z; olo.w += r1.w;
            ohi.x += r2.x; ohi.y += r2.y; ohi.z += r2.z; ohi.w += r2.w;
        }
        *(float4*)&C[(size_t)m * N + bn + tx*4]      = olo;
        *(float4*)&C[(size_t)m * N + bn + 64 + tx*4] = ohi;
    }
}

// ---------------- grep gate: one warp per (b,h,t) ---------------------------
__global__ void gate_kernel(const float* __restrict__ q, const float* __restrict__ gw,
                            const float* __restrict__ gb, const float* __restrict__ ga,
                            float* __restrict__ gate)
{
    __shared__ float sgw[8][64];
    int tid = threadIdx.x;
    ((float*)sgw)[tid]       = gw[tid];
    ((float*)sgw)[tid + 256] = gw[tid + 256];
    __syncthreads();
    int warp = tid >> 5, lane = tid & 31;
    size_t z = (size_t)blockIdx.x * 8 + warp;
    int t = (int)(z % T_);
    int h = (int)((z / T_) % H_);
    int b = (int)(z / ((size_t)H_ * T_));
    const float* qr = q + ((size_t)b * T_ + t) * D_ + h * HD_;
    float q0 = qr[lane] * 256.f;
    float q1 = qr[lane + 32] * 256.f;
    float y[8];
    #pragma unroll
    for (int j = 0; j < 8; j++)
        y[j] = q0 * sgw[j][lane] + q1 * sgw[j][lane + 32];
    #pragma unroll
    for (int o = 16; o > 0; o >>= 1)
        #pragma unroll
        for (int j = 0; j < 8; j++) y[j] += __shfl_xor_sync(0xffffffffu, y[j], o);
    if (lane == 0) {
        float s0 = y[0]+y[1]+y[2]+y[3] + gb[0]+gb[1]+gb[2]+gb[3];
        float s1 = y[4]+y[5]+y[6]+y[7] + gb[4]+gb[5]+gb[6]+gb[7];
        float ga_ = 1.f / (1.f + expf(-s0));
        float gbv = 1.f / (1.f + expf(-s1));
        gate[z] = ga_ * (gbv * ga[h] - 1.f) + 2.f;
    }
}

// ---------------- relative-position bias table: pb[h][rel+1023] -------------
__global__ void pbtable_kernel(const float* __restrict__ rel_emb, float* __restrict__ pb)
{
    int i = blockIdx.x * 256 + threadIdx.x;
    if (i >= 2048) return;
    if (i == 2047) {
        for (int h = 0; h < H_; h++) pb[h * 2048 + i] = 0.f;
        return;
    }
    int rel = i - 1023;
    int bucket = (rel > 0) ? 160 : 0;
    int n = abs(rel);
    int idx;
    if (n < 80) {
        idx = bucket + n;
    } else {
        double nf = (double)n;
        int large = 80 + (int)(log(nf / 80.0) / log(10.0) * 80.0);
        if (large > 159) large = 159;
        idx = bucket + large;
    }
    for (int h = 0; h < H_; h++) pb[h * 2048 + i] = rel_emb[idx * H_ + h];
}

// ---------------- pos_bias_out writer: (B*H, T, T) broadcast ----------------
__global__ void posbias_kernel(const float* __restrict__ pb, float* __restrict__ out)
{
    size_t gid = (size_t)blockIdx.x * 256 + threadIdx.x;
    int s4 = (int)(gid & 255);
    int t  = (int)((gid >> 8) & 1023);
    int bh = (int)(gid >> 18);
    int h  = bh & 15;
    const float* row = pb + h * 2048 + 1023 - t;
    int s = s4 * 4;
    float4 o = make_float4(row[s], row[s+1], row[s+2], row[s+3]);
    ((float4*)out)[gid] = o;
}

// ---------------- batched QK^T + gate*pb epilogue (db, conflict-free) -------
// grid (T/128, T/128, BH); K=64, lda=ldb=D_.
__global__ void __launch_bounds__(256, 2) qk_scores(
    const float* __restrict__ q, const float* __restrict__ k,
    const float* __restrict__ gate, const float* __restrict__ pb,
    float* __restrict__ scores)
{
    int z = blockIdx.z;
    int b = z / H_, h = z % H_;
    const float* A  = q + (size_t)b * T_ * D_ + h * HD_;
    const float* Bm = k + (size_t)b * T_ * D_ + h * HD_;
    float* C = scores + (size_t)z * T_ * T_;

    __shared__ float As[2][16][PAD];
    __shared__ float Bs[2][16][PAD];
    __shared__ float pbs[256];
    __shared__ float gs[128];

    int tid = threadIdx.x;
    int bm = blockIdx.y * 128, bn = blockIdx.x * 128;
    int base = bn - bm + 896;
    pbs[tid] = pb[h * 2048 + base + tid];
    if (tid < 128) gs[tid] = gate[(size_t)z * T_ + bm + tid];

    int r0 = tid >> 2;
    int kc = (tid & 3) * 4;
    const float* Ap = A + (size_t)(bm + r0) * D_ + kc;
    const float* Bp = Bm + (size_t)(bn + r0) * D_ + kc;
    int tx = tid & 15, ty = tid >> 4;

    float acc[8][8] = {};
    float4 ra0, ra1, rb0, rb1;

    ra0 = *(const float4*)(Ap);
    ra1 = *(const float4*)(Ap + (size_t)64 * D_);
    rb0 = *(const float4*)(Bp);
    rb1 = *(const float4*)(Bp + (size_t)64 * D_);
    #pragma unroll
    for (int j = 0; j < 4; j++) {
        As[0][kc+j][r0]    = ((float*)&ra0)[j];
        As[0][kc+j][r0+64] = ((float*)&ra1)[j];
        Bs[0][kc+j][r0]    = ((float*)&rb0)[j];
        Bs[0][kc+j][r0+64] = ((float*)&rb1)[j];
    }
    __syncthreads();

    int buf = 0;
    #pragma unroll
    for (int kt = 0; kt < 4; ++kt) {
        if (kt + 1 < 4) {
            const float* Ap2 = Ap + (kt + 1) * 16;
            const float* Bp2 = Bp + (kt + 1) * 16;
            ra0 = *(const float4*)(Ap2);
            ra1 = *(const float4*)(Ap2 + (size_t)64 * D_);
            rb0 = *(const float4*)(Bp2);
            rb1 = *(const float4*)(Bp2 + (size_t)64 * D_);
        }
        #pragma unroll
        for (int kk = 0; kk < 16; kk++) {
            float a[8], bb[8];
            *(float4*)(a)    = *(const float4*)&As[buf][kk][ty*4];
            *(float4*)(a+4)  = *(const float4*)&As[buf][kk][64 + ty*4];
            *(float4*)(bb)   = *(const float4*)&Bs[buf][kk][tx*4];
            *(float4*)(bb+4) = *(const float4*)&Bs[buf][kk][64 + tx*4];
            #pragma unroll
            for (int i = 0; i < 8; i++)
                #pragma unroll
                for (int j = 0; j < 8; j++) acc[i][j] += a[i] * bb[j];
        }
        if (kt + 1 < 4) {
            buf ^= 1;
            #pragma unroll
            for (int j = 0; j < 4; j++) {
                As[buf][kc+j][r0]    = ((float*)&ra0)[j];
                As[buf][kc+j][r0+64] = ((float*)&ra1)[j];
                Bs[buf][kc+j][r0]    = ((float*)&rb0)[j];
                Bs[buf][kc+j][r0+64] = ((float*)&rb1)[j];
            }
            __syncthreads();
        }
    }

    #pragma unroll
    for (int i = 0; i < 8; i++) {
        int mloc = (i < 4) ? (ty*4 + i) : (64 + ty*4 + i - 4);
        float gv = gs[mloc];
        float4 olo, ohi;
        {
            int n0 = tx*4;
            olo.x = acc[i][0] + gv * pbs[n0+0 - mloc + 127];
            olo.y = acc[i][1] + gv * pbs[n0+1 - mloc + 127];
            olo.z = acc[i][2] + gv * pbs[n0+2 - mloc + 127];
            olo.w = acc[i][3] + gv * pbs[n0+3 - mloc + 127];
            int n1 = 64 + tx*4;
            ohi.x = acc[i][4] + gv * pbs[n1+0 - mloc + 127];
            ohi.y = acc[i][5] + gv * pbs[n1+1 - mloc + 127];
            ohi.z = acc[i][6] + gv * pbs[n1+2 - mloc + 127];
            ohi.w = acc[i][7] + gv * pbs[n1+3 - mloc + 127];
        }
        *(float4*)&C[(size_t)(bm + mloc) * T_ + bn + tx*4]      = olo;
        *(float4*)&C[(size_t)(bm + mloc) * T_ + bn + 64 + tx*4] = ohi;
    }
}

// ---------------- softmax row stats: {max, 1/sum(exp)} ----------------------
__global__ void softmax_stats(const float* __restrict__ s, float2* __restrict__ stats)
{
    size_t row = blockIdx.x;
    const float4* p = (const float4*)(s + row * (size_t)T_);
    int tid = threadIdx.x;
    float4 v = p[tid];
    __shared__ float sm[8];
    __shared__ float bmax, bsum;
    float m = fmaxf(fmaxf(v.x, v.y), fmaxf(v.z, v.w));
    m = warp_max(m);
    if ((tid & 31) == 0) sm[tid >> 5] = m;
    __syncthreads();
    if (tid == 0) {
        float t = sm[0];
        #pragma unroll
        for (int i = 1; i < 8; i++) t = fmaxf(t, sm[i]);
        bmax = t;
    }
    __syncthreads();
    m = bmax;
    float su = __expf(v.x - m) + __expf(v.y - m) + __expf(v.z - m) + __expf(v.w - m);
    su = warp_sum(su);
    __syncthreads();
    if ((tid & 31) == 0) sm[tid >> 5] = su;
    __syncthreads();
    if (tid == 0) {
        float t = 0.f;
        #pragma unroll
        for (int i = 0; i < 8; i++) t += sm[i];
        bsum = t;
    }
    __syncthreads();
    if (tid == 0) stats[row] = make_float2(m, 1.f / bsum);
}

// ---------------- attn·V with fused softmax normalization -------------------
// ctx[t,d] = sum_s exp(sc[t,s]-m[t])*inv[t] * v[s,d].  BM=128,BN=64,BK=16, db.
__global__ void __launch_bounds__(256, 2) av_gemm(
    const float* __restrict__ sc, const float2* __restrict__ stats,
    const float* __restrict__ v, float* __restrict__ ctx)
{
    int z = blockIdx.z;
    int b = z / H_, h = z % H_;
    const float* A  = sc + (size_t)z * T_ * T_;              // lda = T
    const float* Bm = v + (size_t)b * T_ * D_ + h * HD_;     // ldb = D
    float* C = ctx + (size_t)b * T_ * D_ + h * HD_;          // ldc = D

    __shared__ float As[2][16][PAD];
    __shared__ float Bs[2][16][68];
    int tid = threadIdx.x;
    int bm = blockIdx.y * 128;
    int tx = tid & 15, ty = tid >> 4;
    int r0 = tid >> 2;              // 0..63 (A rows)
    int kc = (tid & 3) * 4;         // A k-chunk
    int bkr = tid >> 4;             // 0..15 (B k-row)
    int bcol = (tid & 15) * 4;      // B col

    float2 st0 = stats[(size_t)z * T_ + bm + r0];
    float2 st1 = stats[(size_t)z * T_ + bm + r0 + 64];

    const float* Ap = A + (size_t)(bm + r0) * T_ + kc;

    float acc[8][4] = {};
    float4 ra0, ra1, rb;

    // prologue
    ra0 = *(const float4*)(Ap);
    ra1 = *(const float4*)(Ap + (size_t)64 * T_);
    rb  = *(const float4*)(Bm + (size_t)bkr * D_ + bcol);
    {
        float4 e0, e1;
        e0.x = __expf(ra0.x - st0.x) * st0.y; e0.y = __expf(ra0.y - st0.x) * st0.y;
        e0.z = __expf(ra0.z - st0.x) * st0.y; e0.w = __expf(ra0.w - st0.x) * st0.y;
        e1.x = __expf(ra1.x - st1.x) * st1.y; e1.y = __expf(ra1.y - st1.x) * st1.y;
        e1.z = __expf(ra1.z - st1.x) * st1.y; e1.w = __expf(ra1.w - st1.x) * st1.y;
        #pragma unroll
        for (int j = 0; j < 4; j++) {
            As[0][kc+j][r0]    = ((float*)&e0)[j];
            As[0][kc+j][r0+64] = ((float*)&e1)[j];
        }
        *(float4*)&Bs[0][bkr][bcol] = rb;
    }
    __syncthreads();

    int buf = 0;
    for (int kt = 0; kt < 64; ++kt) {
        if (kt + 1 < 64) {
            ra0 = *(const float4*)(Ap + (kt + 1) * 16);
            ra1 = *(const float4*)(Ap + (kt + 1) * 16 + (size_t)64 * T_);
            rb  = *(const float4*)(Bm + (size_t)((kt + 1) * 16 + bkr) * D_ + bcol);
        }
        #pragma unroll
        for (int kk = 0; kk < 16; kk++) {
            float a[8], bb[4];
            *(float4*)(a)   = *(const float4*)&As[buf][kk][ty*4];
            *(float4*)(a+4) = *(const float4*)&As[buf][kk][64 + ty*4];
            *(float4*)(bb)  = *(const float4*)&Bs[buf][kk][tx*4];
            #pragma unroll
            for (int i = 0; i < 8; i++)
                #pragma unroll
                for (int j = 0; j < 4; j++) acc[i][j] += a[i] * bb[j];
        }
        if (kt + 1 < 64) {
            buf ^= 1;
            float4 e0, e1;
            e0.x = __expf(ra0.x - st0.x) * st0.y; e0.y = __expf(ra0.y - st0.x) * st0.y;
            e0.z = __expf(ra0.z - st0.x) * st0.y; e0.w = __expf(ra0.w - st0.x) * st0.y;
            e1.x = __expf(ra1.x - st1.x) * st1.y; e1.y = __expf(ra1.y - st1.x) * st1.y;
            e1.z = __expf(ra1.z - st1.x) * st1.y; e1.w = __expf(ra1.w - st1.x) * st1.y;
            #pragma unroll
            for (int j = 0; j < 4; j++) {
                As[buf][kc+j][r0]    = ((float*)&e0)[j];
                As[buf][kc+j][r0+64] = ((float*)&e1)[j];
            }
            *(float4*)&Bs[buf][bkr][bcol] = rb;
            __syncthreads();
        }
    }

    #pragma unroll
    for (int i = 0; i < 8; i++) {
        int mloc = (i < 4) ? (ty*4 + i) : (64 + ty*4 + i - 4);
        float4 o = make_float4(acc[i][0], acc[i][1], acc[i][2], acc[i][3]);
        *(float4*)&C[(size_t)(bm + mloc) * D_ + tx*4] = o;
    }
}

// ---------------- host launcher ---------------------------------------------
extern "C" void kernel_launch(void* const* d_in, const int* in_sizes, int n_in,
                              void* d_out, int out_size)
{
    const float* x      = (const float*)d_in[0];
    const float* ln_w   = (const float*)d_in[1];
    const float* ln_b   = (const float*)d_in[2];
    const float* wq     = (const float*)d_in[3];
    const float* bq     = (const float*)d_in[4];
    const float* wk     = (const float*)d_in[5];
    const float* bk     = (const float*)d_in[6];
    const float* wv     = (const float*)d_in[7];
    const float* bv     = (const float*)d_in[8];
    const float* wo     = (const float*)d_in[9];
    const float* bo     = (const float*)d_in[10];
    const float* rel_e  = (const float*)d_in[11];
    const float* grep_w = (const float*)d_in[12];
    const float* grep_b = (const float*)d_in[13];
    const float* grep_a = (const float*)d_in[14];

    float* out     = (float*)d_out;
    float* pos_out = out + (size_t)B_ * T_ * D_;

    float *p_h, *p_q, *p_k, *p_v, *p_ctx, *p_gate, *p_pb, *p_sc;
    float2* p_st;
    cudaGetSymbolAddress((void**)&p_h,    g_h);
    cudaGetSymbolAddress((void**)&p_q,    g_q);
    cudaGetSymbolAddress((void**)&p_k,    g_k);
    cudaGetSymbolAddress((void**)&p_v,    g_v);
    cudaGetSymbolAddress((void**)&p_ctx,  g_ctx);
    cudaGetSymbolAddress((void**)&p_gate, g_gate);
    cudaGetSymbolAddress((void**)&p_pb,   g_pb);
    cudaGetSymbolAddress((void**)&p_st,   g_stats);
    cudaGetSymbolAddress((void**)&p_sc,   g_scores);

    // 1. LayerNorm
    ln_kernel<<<B_*T_, 256>>>(x, ln_w, ln_b, p_h);

    // 2. QKV projections (NT GEMMs); q carries scaling = 64^-0.5
    dim3 g1(D_/128, (B_*T_)/128);
    sgemm_nt_db<<<g1, 256>>>(p_h, wq, bq, nullptr, 0.125f, p_q, B_*T_, D_, D_);
    sgemm_nt_db<<<g1, 256>>>(p_h, wk, bk, nullptr, 1.0f,   p_k, B_*T_, D_, D_);
    sgemm_nt_db<<<g1, 256>>>(p_h, wv, bv, nullptr, 1.0f,   p_v, B_*T_, D_, D_);

    // 3. grep gate
    gate_kernel<<<(BH_*T_)/8, 256>>>(p_q, grep_w, grep_b, grep_a, p_gate);

    // 4. rel-position bias table + broadcast output
    pbtable_kernel<<<8, 256>>>(rel_e, p_pb);
    posbias_kernel<<<65536, 256>>>(p_pb, pos_out);

    // 5. scores = q k^T + gate * pos_bias
    qk_scores<<<dim3(T_/128, T_/128, BH_), 256>>>(p_q, p_k, p_gate, p_pb, p_sc);

    // 6. softmax row stats only (normalization fused into av_gemm)
    softmax_stats<<<BH_*T_, 256>>>(p_sc, p_st);

    // 7. ctx = softmax(scores) @ v   (written directly in (B,T,D) layout)
    av_gemm<<<dim3(1, T_/128, BH_), 256>>>(p_sc, p_st, p_v, p_ctx);

    // 8. out = ctx @ wo^T + bo + x
    sgemm_nt_db<<<g1, 256>>>(p_ctx, wo, bo, x, 1.0f, out, B_*T_, D_, D_);
}